// round 2
// baseline (speedup 1.0000x reference)
#include <cuda_runtime.h>
#include <math.h>

// Problem constants
#define NV    5000
#define NFC   10000
#define CC    128
#define LAYERS 30
#define NNZT  480000
#define EPSBN 1e-5f

// ---------------- device scratch (static, no runtime alloc) ----------------
__device__ float g_v   [NV  * CC];        // vertex features
__device__ float g_f   [NFC * CC];        // face features
__device__ float g_cat0[NFC * 2 * CC];    // [f_in | Dv]
__device__ float g_cat1[NV  * 2 * CC];    // [x_in | DAf] / [elu(x) | avg]
__device__ float g_ef  [NFC * CC];        // elu(f_out) / odd-layer scratch
__device__ float g_stat[512];             // col sums [0:256), sumsq [256:512)
__device__ float g_a   [256];             // folded BN scale
__device__ float g_t   [256];             // beta - mean*a
__device__ float g_bias[128];             // folded GEMM bias
__device__ float g_pool[129];             // 128 col sums + mask sum
__device__ float g_bout[1];               // final scalar bias

__device__ __forceinline__ float eluf(float x) {
    return x > 0.f ? x : (expf(x) - 1.f);
}

// ---------------- elementwise ----------------
__global__ void k_elu_copy(const float* __restrict__ in, int ld_in,
                           float* __restrict__ out, int ld_out, int off, int rows) {
    int idx = blockIdx.x * blockDim.x + threadIdx.x;
    if (idx >= rows * CC) return;
    int r = idx >> 7, c = idx & 127;
    out[r * ld_out + off + c] = eluf(in[r * ld_in + c]);
}

__global__ void k_zero_half(float* __restrict__ out, int ld, int off, int rows) {
    int idx = blockIdx.x * blockDim.x + threadIdx.x;
    if (idx >= rows * CC) return;
    int r = idx >> 7, c = idx & 127;
    out[r * ld + off + c] = 0.f;
}

// ---------------- input projection: v = inputs @ W_in + b_in ----------------
__global__ void k_in(const float* __restrict__ in, const float* __restrict__ Wi,
                     const float* __restrict__ bi) {
    int idx = blockIdx.x * blockDim.x + threadIdx.x;
    if (idx >= NV * CC) return;
    int n = idx >> 7, c = idx & 127;
    float s = bi[c] + in[n * 3 + 0] * Wi[c]
                    + in[n * 3 + 1] * Wi[128 + c]
                    + in[n * 3 + 2] * Wi[256 + c];
    g_v[idx] = s;
}

// ---------------- COO spMM: warp per edge, 32 channels (C//4) ----------------
// Quaternion view: X32[R][d] = base[(R>>2)*ld + off + (R&3)*32 + d]
__global__ void k_spmm(const int* __restrict__ rows_, const int* __restrict__ cols_,
                       const float* __restrict__ vals,
                       const float* __restrict__ X, int ld_in, int off_in,
                       float* __restrict__ Y, int ld_out, int off_out, int nnz) {
    int idx = blockIdx.x * blockDim.x + threadIdx.x;
    int e = idx >> 5, d = idx & 31;
    if (e >= nnz) return;
    int R = rows_[e];
    int Cq = cols_[e];
    float val = vals[e];
    float x = X[(Cq >> 2) * ld_in + off_in + ((Cq & 3) << 5) + d];
    atomicAdd(&Y[(R >> 2) * ld_out + off_out + ((R & 3) << 5) + d], val * x);
}

// ---------------- BN stats: per-channel sum + sumsq (Ch == ld, Ch == blockDim) ----
__global__ void k_stats(const float* __restrict__ X, int ld, int rows) {
    int c = threadIdx.x;
    float s = 0.f, s2 = 0.f;
    for (int r = blockIdx.x; r < rows; r += gridDim.x) {
        float x = X[r * ld + c];
        s += x; s2 += x * x;
    }
    atomicAdd(&g_stat[c], s);
    atomicAdd(&g_stat[256 + c], s2);
}

__global__ void k_prep(const float* __restrict__ gamma, const float* __restrict__ beta,
                       int Ch, float inv_count) {
    int c = threadIdx.x;
    if (c >= Ch) return;
    float mean = g_stat[c] * inv_count;
    float var  = g_stat[256 + c] * inv_count - mean * mean;
    var = fmaxf(var, 0.f);   // one-pass cancellation can drive var slightly negative
    float a = gamma[c] * rsqrtf(var + EPSBN);
    g_a[c] = a;
    g_t[c] = beta[c] - mean * a;
}

__global__ void k_bias(const float* __restrict__ W, const float* __restrict__ b) {
    int j = threadIdx.x;  // 128
    float s = b[j];
    for (int c = 0; c < 256; c++) s += g_t[c] * W[c * 128 + j];
    g_bias[j] = s;
}

// ---------------- fused BN+GEMM: C = (A * a) @ W + bias (+C) ----------------
// A [rows,256] (lda), W [256,128], C [rows,128] (ldc)
__global__ void k_gemm(const float* __restrict__ A, int lda, int rows,
                       const float* __restrict__ W,
                       float* __restrict__ C, int ldc, int accum) {
    __shared__ __align__(16) float As[16][65];
    __shared__ __align__(16) float Bs[16][128];
    __shared__ float sSc[256];
    int tid = threadIdx.x;      // 256
    sSc[tid] = g_a[tid];
    __syncthreads();

    int row0 = blockIdx.x * 64;
    int wc = tid & 31, wr = tid >> 5;
    float acc[8][4];
#pragma unroll
    for (int i = 0; i < 8; i++)
#pragma unroll
        for (int j = 0; j < 4; j++) acc[i][j] = 0.f;

    for (int k0 = 0; k0 < 256; k0 += 16) {
        {   // A tile 64x16: one float4 per thread
            int m = tid >> 2, k4 = (tid & 3) * 4;
            int r = row0 + m;
            float4 va = make_float4(0.f, 0.f, 0.f, 0.f);
            if (r < rows) va = *(const float4*)&A[r * lda + k0 + k4];
            As[k4 + 0][m] = va.x * sSc[k0 + k4 + 0];
            As[k4 + 1][m] = va.y * sSc[k0 + k4 + 1];
            As[k4 + 2][m] = va.z * sSc[k0 + k4 + 2];
            As[k4 + 3][m] = va.w * sSc[k0 + k4 + 3];
        }
#pragma unroll
        for (int i = 0; i < 2; i++) {  // B tile 16x128: two float4 per thread
            int l = tid + i * 256;
            int k = l >> 5, c4 = (l & 31) * 4;
            float4 vb = *(const float4*)&W[(k0 + k) * 128 + c4];
            *(float4*)&Bs[k][c4] = vb;
        }
        __syncthreads();
#pragma unroll
        for (int k = 0; k < 16; k++) {
            float4 b4 = *(float4*)&Bs[k][wc * 4];
            float ar[8];
#pragma unroll
            for (int i = 0; i < 8; i++) ar[i] = As[k][wr * 8 + i];
#pragma unroll
            for (int i = 0; i < 8; i++) {
                acc[i][0] += ar[i] * b4.x;
                acc[i][1] += ar[i] * b4.y;
                acc[i][2] += ar[i] * b4.z;
                acc[i][3] += ar[i] * b4.w;
            }
        }
        __syncthreads();
    }
#pragma unroll
    for (int i = 0; i < 8; i++) {
        int r = row0 + wr * 8 + i;
        if (r >= rows) continue;
#pragma unroll
        for (int j = 0; j < 4; j++) {
            int c = wc * 4 + j;
            float v = acc[i][j] + g_bias[c];
            if (accum) v += C[r * ldc + c];
            C[r * ldc + c] = v;
        }
    }
}

// ---------------- masked average pooling ----------------
__global__ void k_pool(const float* __restrict__ X, int ld,
                       const float* __restrict__ mask, int rows) {
    int c = threadIdx.x;  // 128
    float s = 0.f, ms = 0.f;
    for (int r = blockIdx.x; r < rows; r += gridDim.x) {
        float m = mask[r];
        s += X[r * ld + c] * m;
        if (c == 0) ms += m;
    }
    atomicAdd(&g_pool[c], s);
    if (c == 0) atomicAdd(&g_pool[128], ms);
}

__global__ void k_bcast(float* __restrict__ out, int ld, int off, int rows) {
    int idx = blockIdx.x * blockDim.x + threadIdx.x;
    if (idx >= rows * CC) return;
    int r = idx >> 7, c = idx & 127;
    out[r * ld + off + c] = g_pool[c] / g_pool[128];
}

// ---------------- final head ----------------
__global__ void k_prep2(const float* __restrict__ Wout, const float* __restrict__ bout) {
    __shared__ float sh[128];
    int c = threadIdx.x;
    sh[c] = g_t[c] * Wout[c];
    __syncthreads();
    for (int s = 64; s > 0; s >>= 1) {
        if (c < s) sh[c] += sh[c + s];
        __syncthreads();
    }
    if (c == 0) g_bout[0] = bout[0] + sh[0];
}

__global__ void k_final(const float* __restrict__ Wout, float* __restrict__ out) {
    int warp = (blockIdx.x * blockDim.x + threadIdx.x) >> 5;
    int lane = threadIdx.x & 31;
    if (warp >= NV) return;
    float s = 0.f;
#pragma unroll
    for (int q = 0; q < 4; q++) {
        int c = q * 32 + lane;
        s += g_v[warp * 128 + c] * g_a[c] * Wout[c];
    }
#pragma unroll
    for (int o = 16; o; o >>= 1) s += __shfl_xor_sync(0xffffffffu, s, o);
    if (lane == 0) out[warp] = eluf(s + g_bout[0]);
}

// ---------------- host orchestration ----------------
extern "C" void kernel_launch(void* const* d_in, const int* in_sizes, int n_in,
                              void* d_out, int out_size) {
    const float* inputs   = (const float*)d_in[0];
    const float* mask     = (const float*)d_in[1];
    const int*   Di_rows  = (const int*)d_in[2];
    const int*   Di_cols  = (const int*)d_in[3];
    const float* Di_vals  = (const float*)d_in[4];
    const int*   DiA_rows = (const int*)d_in[5];
    const int*   DiA_cols = (const int*)d_in[6];
    const float* DiA_vals = (const float*)d_in[7];
    const float* W_in  = (const float*)d_in[8];
    const float* b_in  = (const float*)d_in[9];
    const float* g0    = (const float*)d_in[10];
    const float* be0   = (const float*)d_in[11];
    const float* W0    = (const float*)d_in[12];
    const float* b0    = (const float*)d_in[13];
    const float* g1    = (const float*)d_in[14];
    const float* be1   = (const float*)d_in[15];
    const float* Wl1   = (const float*)d_in[16];
    const float* bl1   = (const float*)d_in[17];
    const float* g2    = (const float*)d_in[18];
    const float* be2   = (const float*)d_in[19];
    const float* W_out = (const float*)d_in[20];
    const float* b_out = (const float*)d_in[21];
    float* out = (float*)d_out;
    (void)in_sizes; (void)n_in; (void)out_size;

    float *p_v, *p_f, *p_cat0, *p_cat1, *p_ef, *p_stat, *p_pool;
    cudaGetSymbolAddress((void**)&p_v,    g_v);
    cudaGetSymbolAddress((void**)&p_f,    g_f);
    cudaGetSymbolAddress((void**)&p_cat0, g_cat0);
    cudaGetSymbolAddress((void**)&p_cat1, g_cat1);
    cudaGetSymbolAddress((void**)&p_ef,   g_ef);
    cudaGetSymbolAddress((void**)&p_stat, g_stat);
    cudaGetSymbolAddress((void**)&p_pool, g_pool);

    const int GE_N  = (NV  * CC + 255) / 256;   // elementwise grid, vertices
    const int GE_F  = (NFC * CC + 255) / 256;   // elementwise grid, faces
    const int GSPMM = (NNZT * 32 + 255) / 256;

    auto bn_gemm = [&](const float* X, int rows,
                       const float* gamma, const float* beta,
                       const float* W, const float* b,
                       float* Cout, int accum) {
        cudaMemsetAsync(p_stat, 0, 512 * sizeof(float));
        k_stats<<<256, 256>>>(X, 256, rows);
        k_prep<<<1, 256>>>(gamma, beta, 256, 1.0f / (float)rows);
        k_bias<<<1, 128>>>(W, b);
        k_gemm<<<(rows + 63) / 64, 256>>>(X, 256, rows, W, Cout, 128, accum);
    };

    // init: f = 0, v = inputs @ W_in + b_in
    cudaMemsetAsync(p_f, 0, (size_t)NFC * CC * sizeof(float));
    k_in<<<GE_N, 256>>>(inputs, W_in, b_in);

    for (int i = 0; i < LAYERS; i++) {
        if ((i & 1) == 0) {
            // ---- DirResNet2 ----
            k_elu_copy<<<GE_N, 256>>>(p_v, 128, p_cat1, 256, 0, NV);     // x_in
            k_elu_copy<<<GE_F, 256>>>(p_f, 128, p_cat0, 256, 0, NFC);    // f_in
            k_zero_half<<<GE_F, 256>>>(p_cat0, 256, 128, NFC);           // Dv = 0
            k_spmm<<<GSPMM, 256>>>(Di_rows, Di_cols, Di_vals,
                                   p_cat1, 256, 0, p_cat0, 256, 128, NNZT);
            bn_gemm(p_cat0, NFC, g0 + i * 256, be0 + i * 256,
                    W0 + (size_t)i * 256 * 128, b0 + i * 128, p_f, 0);   // f_out
            k_elu_copy<<<GE_F, 256>>>(p_f, 128, p_ef, 128, 0, NFC);      // elu(f_out)
            k_zero_half<<<GE_N, 256>>>(p_cat1, 256, 128, NV);            // DAf = 0
            k_spmm<<<GSPMM, 256>>>(DiA_rows, DiA_cols, DiA_vals,
                                   p_ef, 128, 0, p_cat1, 256, 128, NNZT);
            bn_gemm(p_cat1, NV, g1 + i * 256, be1 + i * 256,
                    Wl1 + (size_t)i * 256 * 128, bl1 + i * 128, p_v, 1); // v += ...
        } else {
            // ---- AvgResNet2 ----
            k_elu_copy<<<GE_N, 256>>>(p_v, 128, p_cat1, 256, 0, NV);
            cudaMemsetAsync(p_pool, 0, 129 * sizeof(float));
            k_pool<<<128, 128>>>(p_cat1, 256, mask, NV);
            k_bcast<<<GE_N, 256>>>(p_cat1, 256, 128, NV);
            bn_gemm(p_cat1, NV, g0 + i * 256, be0 + i * 256,
                    W0 + (size_t)i * 256 * 128, b0 + i * 128, p_ef, 0);  // x1 (scratch)

            k_elu_copy<<<GE_N, 256>>>(p_ef, 128, p_cat1, 256, 0, NV);
            cudaMemsetAsync(p_pool, 0, 129 * sizeof(float));
            k_pool<<<128, 128>>>(p_cat1, 256, mask, NV);
            k_bcast<<<GE_N, 256>>>(p_cat1, 256, 128, NV);
            bn_gemm(p_cat1, NV, g1 + i * 256, be1 + i * 256,
                    Wl1 + (size_t)i * 256 * 128, bl1 + i * 128, p_v, 1); // v += ...
        }
    }

    // final head: elu( BN(v) @ W_out + b_out )
    cudaMemsetAsync(p_stat, 0, 512 * sizeof(float));
    k_stats<<<256, 128>>>(p_v, 128, NV);
    k_prep<<<1, 256>>>(g2, be2, 128, 1.0f / (float)NV);
    k_prep2<<<1, 128>>>(W_out, b_out);
    k_final<<<(NV * 32 + 255) / 256, 256>>>(W_out, out);
}

// round 3
// speedup vs baseline: 1.8938x; 1.8938x over previous
#include <cuda_runtime.h>
#include <math.h>

// Problem constants
#define NV    5000
#define NFC   10000
#define LAYERS 30
#define NNZT  480000
#define EPSBN 1e-5f

// ---------------- device scratch ----------------
__device__ __align__(16) float g_v [NV  * 128];  // vertex features (raw)
__device__ __align__(16) float g_ev[NV  * 128];  // elu(v)
__device__ __align__(16) float g_ef[NFC * 128];  // elu(f_out)   (also f_in of next even layer)
__device__ __align__(16) float g_ex[NV  * 128];  // odd-layer elu scratch
__device__ __align__(16) float g_Dv[NFC * 128];  // Dirac vertices->faces
__device__ __align__(16) float g_DA[NV  * 128];  // adjoint Dirac faces->vertices
__device__ float g_stats[3 * 512];               // 3 stat buffers: sum[256] | sumsq[256]
__device__ float g_a   [256];                    // folded BN scale
__device__ float g_bias[128];                    // folded GEMM bias
__device__ float g_bout[1];                      // final scalar bias

__device__ __forceinline__ float eluf(float x) {
    return x > 0.f ? x : (__expf(x) - 1.f);
}

// ---------------- input projection: v = in @ W_in + b; ev = elu(v); stats(ev) ----
__global__ void k_in(const float* __restrict__ in, const float* __restrict__ Wi,
                     const float* __restrict__ bi, float* __restrict__ statp) {
    int c = threadIdx.x;  // 128
    float w0 = Wi[c], w1 = Wi[128 + c], w2 = Wi[256 + c], b = bi[c];
    float s = 0.f, s2 = 0.f;
    for (int n = blockIdx.x; n < NV; n += gridDim.x) {
        float val = b + in[n * 3] * w0 + in[n * 3 + 1] * w1 + in[n * 3 + 2] * w2;
        g_v [n * 128 + c] = val;
        float e = eluf(val);
        g_ev[n * 128 + c] = e;
        s += e; s2 += e * e;
    }
    atomicAdd(&statp[c], s);
    atomicAdd(&statp[256 + c], s2);
}

// ---------------- COO spMM: 8 threads/edge, float4 vector atomics ----------------
// quaternion view: row q -> base[(q>>2)*128 + (q&3)*32 + ...]
__global__ void k_spmm(const int* __restrict__ rows_, const int* __restrict__ cols_,
                       const float* __restrict__ vals,
                       const float* __restrict__ X, float* __restrict__ Y) {
    int idx = blockIdx.x * blockDim.x + threadIdx.x;
    int e = idx >> 3, d = idx & 7;
    if (e >= NNZT) return;
    int R = rows_[e], Cq = cols_[e];
    float v = vals[e];
    float4 xv = ((const float4*)X)[(Cq >> 2) * 32 + (Cq & 3) * 8 + d];
    float4* yp = (float4*)Y + (R >> 2) * 32 + (R & 3) * 8 + d;
    asm volatile("red.global.add.v4.f32 [%0], {%1,%2,%3,%4};"
                 :: "l"(yp), "f"(v * xv.x), "f"(v * xv.y), "f"(v * xv.z), "f"(v * xv.w)
                 : "memory");
}

// ---------------- column stats over a [rows,128] tensor ----------------
__global__ void k_stats128(const float* __restrict__ X, int rows,
                           float* __restrict__ statp, int off) {
    int c = threadIdx.x;  // 128
    float s = 0.f, s2 = 0.f;
    for (int r = blockIdx.x; r < rows; r += gridDim.x) {
        float x = X[r * 128 + c];
        s += x; s2 += x * x;
    }
    atomicAdd(&statp[off + c], s);
    atomicAdd(&statp[256 + off + c], s2);
}

// ---------------- BN fold + bias fold (even layers, K=256) ----------------
__global__ void k_prepbias(float* __restrict__ statp,
                           const float* __restrict__ gamma, const float* __restrict__ beta,
                           const float* __restrict__ W, const float* __restrict__ b,
                           float invn) {
    __shared__ float t_sh[256];
    int tid = threadIdx.x;  // 256
    {
        float mean = statp[tid] * invn;
        float var  = fmaxf(statp[256 + tid] * invn - mean * mean, 0.f);
        float a = gamma[tid] * rsqrtf(var + EPSBN);
        g_a[tid] = a;
        t_sh[tid] = beta[tid] - mean * a;
    }
    __syncthreads();
    if (tid < 128) {
        float s = b[tid];
#pragma unroll 8
        for (int c = 0; c < 256; c++) s += t_sh[c] * W[c * 128 + tid];
        g_bias[tid] = s;
    }
    statp[tid] = 0.f; statp[256 + tid] = 0.f;
}

// ---------------- BN fold + bias fold (odd layers, K=128, avg cols -> beta) ------
__global__ void k_prepbias_odd(float* __restrict__ statp,
                               const float* __restrict__ gamma, const float* __restrict__ beta,
                               const float* __restrict__ W, const float* __restrict__ b,
                               float invn) {
    __shared__ float t_sh[256];
    int tid = threadIdx.x;  // 256
    if (tid < 128) {
        float mean = statp[tid] * invn;
        float var  = fmaxf(statp[256 + tid] * invn - mean * mean, 0.f);
        float a = gamma[tid] * rsqrtf(var + EPSBN);
        g_a[tid] = a;
        t_sh[tid] = beta[tid] - mean * a;
    } else {
        // broadcast-avg columns: zero variance => BN output is exactly beta
        t_sh[tid] = beta[tid];
    }
    __syncthreads();
    if (tid < 128) {
        float s = b[tid];
#pragma unroll 8
        for (int c = 0; c < 256; c++) s += t_sh[c] * W[c * 128 + tid];
        g_bias[tid] = s;
    }
    statp[tid] = 0.f; statp[256 + tid] = 0.f;
}

// ---------------- fused BN+GEMM + elu + stats epilogue ----------------
// out = (A*a) @ W + bias [+ V];  A = [L | R] split pointers, each [rows,128]
// KT = number of 16-wide K tiles (16 -> K=256, 8 -> K=128)
// ACC: also V += out (raw write); always: Eout = elu(out), stats(elu) -> statp[c],[256+c]
template<int KT, bool ACC>
__global__ void __launch_bounds__(256)
k_gemm(const float* __restrict__ L, const float* __restrict__ R,
       int rows, const float* __restrict__ W,
       float* __restrict__ Vout, float* __restrict__ Eout,
       float* __restrict__ statp) {
    __shared__ __align__(16) float As[16][65];
    __shared__ __align__(16) float Bs[16][128];
    __shared__ float sSc[256];
    __shared__ float sB[128];
    int tid = threadIdx.x;  // 256
    sSc[tid] = g_a[tid];
    if (tid < 128) sB[tid] = g_bias[tid];
    __syncthreads();

    int row0 = blockIdx.x * 64;
    int wc = tid & 31, wr = tid >> 5;
    float acc[8][4];
#pragma unroll
    for (int i = 0; i < 8; i++)
#pragma unroll
        for (int j = 0; j < 4; j++) acc[i][j] = 0.f;

#pragma unroll 1
    for (int t = 0; t < KT; t++) {
        int k0 = t * 16;
        const float* Abase = (KT == 16 && k0 >= 128) ? R : L;
        int kk = k0 & 127;
        {   // A tile 64x16
            int m = tid >> 2, k4 = (tid & 3) * 4;
            int r = row0 + m;
            float4 va = make_float4(0.f, 0.f, 0.f, 0.f);
            if (r < rows) va = *(const float4*)&Abase[r * 128 + kk + k4];
            As[k4 + 0][m] = va.x * sSc[k0 + k4 + 0];
            As[k4 + 1][m] = va.y * sSc[k0 + k4 + 1];
            As[k4 + 2][m] = va.z * sSc[k0 + k4 + 2];
            As[k4 + 3][m] = va.w * sSc[k0 + k4 + 3];
        }
#pragma unroll
        for (int i = 0; i < 2; i++) {  // B tile 16x128
            int l = tid + i * 256;
            int k = l >> 5, c4 = (l & 31) * 4;
            *(float4*)&Bs[k][c4] = *(const float4*)&W[(k0 + k) * 128 + c4];
        }
        __syncthreads();
#pragma unroll
        for (int k = 0; k < 16; k++) {
            float4 b4 = *(float4*)&Bs[k][wc * 4];
            float ar[8];
#pragma unroll
            for (int i = 0; i < 8; i++) ar[i] = As[k][wr * 8 + i];
#pragma unroll
            for (int i = 0; i < 8; i++) {
                acc[i][0] += ar[i] * b4.x;
                acc[i][1] += ar[i] * b4.y;
                acc[i][2] += ar[i] * b4.z;
                acc[i][3] += ar[i] * b4.w;
            }
        }
        __syncthreads();
    }

    // epilogue: bias (+accum), elu, per-column stats (reduce in Bs region)
    float s1v[4] = {0.f, 0.f, 0.f, 0.f};
    float s2v[4] = {0.f, 0.f, 0.f, 0.f};
#pragma unroll
    for (int i = 0; i < 8; i++) {
        int r = row0 + wr * 8 + i;
        if (r >= rows) continue;
#pragma unroll
        for (int j = 0; j < 4; j++) {
            int c = wc * 4 + j;
            float val = acc[i][j] + sB[c];
            if (ACC) {
                val += Vout[r * 128 + c];
                Vout[r * 128 + c] = val;
            }
            float e = eluf(val);
            Eout[r * 128 + c] = e;
            s1v[j] += e; s2v[j] += e * e;
        }
    }
    float* red = &Bs[0][0];  // 2048 floats: [0:1024) sums, [1024:2048) sumsq
#pragma unroll
    for (int j = 0; j < 4; j++) {
        red[wr * 128 + wc * 4 + j]        = s1v[j];
        red[1024 + wr * 128 + wc * 4 + j] = s2v[j];
    }
    __syncthreads();
    if (tid < 128) {
        float s = 0.f;
#pragma unroll
        for (int w = 0; w < 8; w++) s += red[w * 128 + tid];
        atomicAdd(&statp[tid], s);
    } else {
        int c = tid - 128;
        float s = 0.f;
#pragma unroll
        for (int w = 0; w < 8; w++) s += red[1024 + w * 128 + c];
        atomicAdd(&statp[256 + c], s);
    }
}

// ---------------- final head ----------------
__global__ void k_head_prep(const float* __restrict__ gamma, const float* __restrict__ beta,
                            const float* __restrict__ Wout, const float* __restrict__ bout,
                            float* __restrict__ statp, float invn) {
    __shared__ float sh[128];
    int c = threadIdx.x;  // 128
    float mean = statp[c] * invn;
    float var  = fmaxf(statp[256 + c] * invn - mean * mean, 0.f);
    float a = gamma[c] * rsqrtf(var + EPSBN);
    g_a[c] = a;
    sh[c] = (beta[c] - mean * a) * Wout[c];
    __syncthreads();
    for (int s = 64; s > 0; s >>= 1) {
        if (c < s) sh[c] += sh[c + s];
        __syncthreads();
    }
    if (c == 0) g_bout[0] = bout[0] + sh[0];
    statp[c] = 0.f; statp[128 + c] = 0.f; statp[256 + c] = 0.f; statp[384 + c] = 0.f;
}

__global__ void k_final(const float* __restrict__ Wout, float* __restrict__ out) {
    int warp = (blockIdx.x * blockDim.x + threadIdx.x) >> 5;
    int lane = threadIdx.x & 31;
    if (warp >= NV) return;
    float s = 0.f;
#pragma unroll
    for (int q = 0; q < 4; q++) {
        int c = q * 32 + lane;
        s += g_v[warp * 128 + c] * g_a[c] * Wout[c];
    }
#pragma unroll
    for (int o = 16; o; o >>= 1) s += __shfl_xor_sync(0xffffffffu, s, o);
    if (lane == 0) out[warp] = eluf(s + g_bout[0]);
}

// ---------------- host orchestration ----------------
extern "C" void kernel_launch(void* const* d_in, const int* in_sizes, int n_in,
                              void* d_out, int out_size) {
    const float* inputs   = (const float*)d_in[0];
    // d_in[1] = mask: provably irrelevant (avg columns fold to beta exactly)
    const int*   Di_rows  = (const int*)d_in[2];
    const int*   Di_cols  = (const int*)d_in[3];
    const float* Di_vals  = (const float*)d_in[4];
    const int*   DiA_rows = (const int*)d_in[5];
    const int*   DiA_cols = (const int*)d_in[6];
    const float* DiA_vals = (const float*)d_in[7];
    const float* W_in  = (const float*)d_in[8];
    const float* b_in  = (const float*)d_in[9];
    const float* g0    = (const float*)d_in[10];
    const float* be0   = (const float*)d_in[11];
    const float* W0    = (const float*)d_in[12];
    const float* b0    = (const float*)d_in[13];
    const float* g1    = (const float*)d_in[14];
    const float* be1   = (const float*)d_in[15];
    const float* Wl1   = (const float*)d_in[16];
    const float* bl1   = (const float*)d_in[17];
    const float* g2    = (const float*)d_in[18];
    const float* be2   = (const float*)d_in[19];
    const float* W_out = (const float*)d_in[20];
    const float* b_out = (const float*)d_in[21];
    float* out = (float*)d_out;
    (void)in_sizes; (void)n_in; (void)out_size;

    float *p_v, *p_ev, *p_ef, *p_ex, *p_Dv, *p_DA, *p_stats;
    cudaGetSymbolAddress((void**)&p_v,     g_v);
    cudaGetSymbolAddress((void**)&p_ev,    g_ev);
    cudaGetSymbolAddress((void**)&p_ef,    g_ef);
    cudaGetSymbolAddress((void**)&p_ex,    g_ex);
    cudaGetSymbolAddress((void**)&p_Dv,    g_Dv);
    cudaGetSymbolAddress((void**)&p_DA,    g_DA);
    cudaGetSymbolAddress((void**)&p_stats, g_stats);
    float* S0 = p_stats;            // even gemm1 stats: [ef | Dv]
    float* S1 = p_stats + 512;      // even gemm2 stats: [ev | DAf]
    float* SO = p_stats + 1024;     // odd-layer + head stats

    const int GF = (NFC + 63) / 64;   // 157
    const int GN = (NV  + 63) / 64;   // 79
    const int GS = (NNZT * 8 + 255) / 256;
    const float INV_F = 1.0f / (float)NFC;
    const float INV_N = 1.0f / (float)NV;

    // replay-invariant init
    cudaMemsetAsync(p_stats, 0, 3 * 512 * sizeof(float));
    cudaMemsetAsync(p_ef, 0, (size_t)NFC * 128 * sizeof(float));   // f(0)=0 -> elu=0
    k_in<<<128, 128>>>(inputs, W_in, b_in, S1);                    // v, ev, stats(ev)->S1

    for (int i = 0; i < LAYERS; i++) {
        const float* W0i  = W0  + (size_t)i * 256 * 128;
        const float* Wl1i = Wl1 + (size_t)i * 256 * 128;
        if ((i & 1) == 0) {
            // ---- DirResNet2 ----
            cudaMemsetAsync(p_Dv, 0, (size_t)NFC * 128 * sizeof(float));
            k_spmm<<<GS, 256>>>(Di_rows, Di_cols, Di_vals, p_ev, p_Dv);
            k_stats128<<<256, 128>>>(p_Dv, NFC, S0, 128);
            k_prepbias<<<1, 256>>>(S0, g0 + i * 256, be0 + i * 256, W0i, b0 + i * 128, INV_F);
            // f_out; write ef=elu(f_out) in place; stats(ef)->S0 left (for next even layer)
            k_gemm<16, false><<<GF, 256>>>(p_ef, p_Dv, NFC, W0i, nullptr, p_ef, S0);
            cudaMemsetAsync(p_DA, 0, (size_t)NV * 128 * sizeof(float));
            k_spmm<<<GS, 256>>>(DiA_rows, DiA_cols, DiA_vals, p_ef, p_DA);
            k_stats128<<<256, 128>>>(p_DA, NV, S1, 128);
            k_prepbias<<<1, 256>>>(S1, g1 + i * 256, be1 + i * 256, Wl1i, bl1 + i * 128, INV_N);
            // v += ...; ev = elu(v); stats(ev)->SO (for next odd layer)
            k_gemm<16, true><<<GN, 256>>>(p_ev, p_DA, NV, Wl1i, p_v, p_ev, SO);
        } else {
            // ---- AvgResNet2 (avg columns folded to beta; K halved) ----
            k_prepbias_odd<<<1, 256>>>(SO, g0 + i * 256, be0 + i * 256, W0i, b0 + i * 128, INV_N);
            k_gemm<8, false><<<GN, 256>>>(p_ev, nullptr, NV, W0i, nullptr, p_ex, SO);
            k_prepbias_odd<<<1, 256>>>(SO, g1 + i * 256, be1 + i * 256, Wl1i, bl1 + i * 128, INV_N);
            // v += ...; ev = elu(v); stats(ev)->S1 left (for next even layer)
            k_gemm<8, true><<<GN, 256>>>(p_ex, nullptr, NV, Wl1i, p_v, p_ev, S1);
        }
    }

    // final head: elu( BN(v) @ W_out + b_out )
    k_stats128<<<256, 128>>>(p_v, NV, SO, 0);
    k_head_prep<<<1, 128>>>(g2, be2, W_out, b_out, SO, INV_N);
    k_final<<<(NV * 32 + 255) / 256, 256>>>(W_out, out);
}

// round 4
// speedup vs baseline: 2.2470x; 1.1865x over previous
#include <cuda_runtime.h>
#include <math.h>

// Problem constants
#define NV    5000
#define NFC   10000
#define LAYERS 30
#define NNZT  480000
#define EPSBN 1e-5f

// ---------------- device scratch ----------------
__device__ __align__(16) float g_v [NV  * 128];  // vertex features (raw)
__device__ __align__(16) float g_ev[NV  * 128];  // elu(v)
__device__ __align__(16) float g_ef[NFC * 128];  // elu(f_out)
__device__ __align__(16) float g_ex[NV  * 128];  // odd-layer elu scratch
__device__ __align__(16) float g_Dv[NFC * 128];  // Dirac vertices->faces
__device__ __align__(16) float g_DA[NV  * 128];  // adjoint Dirac faces->vertices
__device__ float g_stats[64 * 512];              // one-shot stat buffers: sum[256]|sumsq[256]
__device__ float g_a   [128];                    // head BN scale
__device__ float g_bout[1];                      // head scalar bias

__device__ __forceinline__ float eluf(float x) {
    return x > 0.f ? x : (__expf(x) - 1.f);
}

// ---------------- input projection: v = in @ W_in + b; ev = elu(v); stats(ev) ----
__global__ void k_in(const float* __restrict__ in, const float* __restrict__ Wi,
                     const float* __restrict__ bi, float* __restrict__ statp) {
    int c = threadIdx.x;  // 128
    float w0 = Wi[c], w1 = Wi[128 + c], w2 = Wi[256 + c], b = bi[c];
    float s = 0.f, s2 = 0.f;
    for (int n = blockIdx.x; n < NV; n += gridDim.x) {
        float val = b + in[n * 3] * w0 + in[n * 3 + 1] * w1 + in[n * 3 + 2] * w2;
        g_v [n * 128 + c] = val;
        float e = eluf(val);
        g_ev[n * 128 + c] = e;
        s += e; s2 += e * e;
    }
    atomicAdd(&statp[c], s);
    atomicAdd(&statp[256 + c], s2);
}

// ---------------- COO spMM: 8 threads/edge, float4 vector atomics ----------------
__global__ void k_spmm(const int* __restrict__ rows_, const int* __restrict__ cols_,
                       const float* __restrict__ vals,
                       const float* __restrict__ X, float* __restrict__ Y) {
    int idx = blockIdx.x * blockDim.x + threadIdx.x;
    int e = idx >> 3, d = idx & 7;
    if (e >= NNZT) return;
    int R = rows_[e], Cq = cols_[e];
    float v = vals[e];
    float4 xv = ((const float4*)X)[(Cq >> 2) * 32 + (Cq & 3) * 8 + d];
    float4* yp = (float4*)Y + (R >> 2) * 32 + (R & 3) * 8 + d;
    asm volatile("red.global.add.v4.f32 [%0], {%1,%2,%3,%4};"
                 :: "l"(yp), "f"(v * xv.x), "f"(v * xv.y), "f"(v * xv.z), "f"(v * xv.w)
                 : "memory");
}

// ---------------- column stats over a [rows,128] tensor ----------------
__global__ void k_stats128(const float* __restrict__ X, int rows,
                           float* __restrict__ statp, int off) {
    int c = threadIdx.x;  // 128
    float s = 0.f, s2 = 0.f;
    for (int r = blockIdx.x; r < rows; r += gridDim.x) {
        float x = X[r * 128 + c];
        s += x; s2 += x * x;
    }
    atomicAdd(&statp[off + c], s);
    atomicAdd(&statp[256 + off + c], s2);
}

// ---------------- fused BN-fold + bias-fold + GEMM + elu + stats epilogue --------
// out = (A*a) @ W + bias [+ V];  A = [L | R] split pointers, each [rows,128]
// KT=16 -> K=256 (both halves from stats); KT=8 -> K=128 (right half folds to beta)
// Prologue: a,t from statp_in; bias accumulated from W tiles during main loop.
// Epilogue: [ACC: V += out], Eout = elu(out), column stats(elu) -> statp_out.
template<int KT, bool ACC>
__global__ void __launch_bounds__(256)
k_gemm(const float* __restrict__ L, const float* __restrict__ R, int rows,
       const float* __restrict__ W, const float* __restrict__ bvec,
       const float* __restrict__ gamma, const float* __restrict__ beta,
       const float* __restrict__ statp_in, float invn,
       float* __restrict__ Vout, float* __restrict__ Eout,
       float* __restrict__ statp_out) {
    __shared__ __align__(16) float As[16][65];
    __shared__ __align__(16) float Bs[16][128];
    __shared__ float sSc[256];
    __shared__ float sT [256];
    __shared__ float sB [128];
    int tid = threadIdx.x;  // 256

    // prologue: BN fold (redundant per block, ~1KB reads)
    if (KT == 16 || tid < 128) {
        float mean = statp_in[tid] * invn;
        float var  = fmaxf(statp_in[256 + tid] * invn - mean * mean, 0.f);
        float a = gamma[tid] * rsqrtf(var + EPSBN);
        sSc[tid] = a;
        sT[tid]  = beta[tid] - mean * a;
    } else {
        sT[tid] = beta[tid];   // broadcast-avg columns: var==0 -> BN out == beta
    }
    __syncthreads();

    int row0 = blockIdx.x * 64;
    int wc = tid & 31, wr = tid >> 5;
    float acc[8][4];
#pragma unroll
    for (int i = 0; i < 8; i++)
#pragma unroll
        for (int j = 0; j < 4; j++) acc[i][j] = 0.f;
    float biasAcc = 0.f;

#pragma unroll 1
    for (int t = 0; t < KT; t++) {
        int k0 = t * 16;
        const float* Abase = (KT == 16 && k0 >= 128) ? R : L;
        int kk = k0 & 127;
        {   // A tile 64x16
            int m = tid >> 2, k4 = (tid & 3) * 4;
            int r = row0 + m;
            float4 va = make_float4(0.f, 0.f, 0.f, 0.f);
            if (r < rows) va = *(const float4*)&Abase[r * 128 + kk + k4];
            As[k4 + 0][m] = va.x * sSc[k0 + k4 + 0];
            As[k4 + 1][m] = va.y * sSc[k0 + k4 + 1];
            As[k4 + 2][m] = va.z * sSc[k0 + k4 + 2];
            As[k4 + 3][m] = va.w * sSc[k0 + k4 + 3];
        }
#pragma unroll
        for (int i = 0; i < 2; i++) {  // B tile 16x128
            int l = tid + i * 256;
            int k = l >> 5, c4 = (l & 31) * 4;
            *(float4*)&Bs[k][c4] = *(const float4*)&W[(k0 + k) * 128 + c4];
        }
        __syncthreads();

        if (tid < 128) {  // bias fold rides on the resident W tile
#pragma unroll
            for (int k = 0; k < 16; k++) biasAcc += sT[k0 + k] * Bs[k][tid];
        }
#pragma unroll
        for (int k = 0; k < 16; k++) {
            float4 b4 = *(float4*)&Bs[k][wc * 4];
            float ar[8];
#pragma unroll
            for (int i = 0; i < 8; i++) ar[i] = As[k][wr * 8 + i];
#pragma unroll
            for (int i = 0; i < 8; i++) {
                acc[i][0] += ar[i] * b4.x;
                acc[i][1] += ar[i] * b4.y;
                acc[i][2] += ar[i] * b4.z;
                acc[i][3] += ar[i] * b4.w;
            }
        }
        __syncthreads();
    }

    if (tid < 128) sB[tid] = biasAcc + bvec[tid];
    __syncthreads();

    // epilogue: bias (+accum), elu, per-column stats
    float s1v[4] = {0.f, 0.f, 0.f, 0.f};
    float s2v[4] = {0.f, 0.f, 0.f, 0.f};
#pragma unroll
    for (int i = 0; i < 8; i++) {
        int r = row0 + wr * 8 + i;
        if (r >= rows) continue;
#pragma unroll
        for (int j = 0; j < 4; j++) {
            int c = wc * 4 + j;
            float val = acc[i][j] + sB[c];
            if (ACC) {
                val += Vout[r * 128 + c];
                Vout[r * 128 + c] = val;
            }
            float e = eluf(val);
            Eout[r * 128 + c] = e;
            s1v[j] += e; s2v[j] += e * e;
        }
    }
    float* red = &Bs[0][0];  // 2048 floats: [0:1024) sums, [1024:2048) sumsq
#pragma unroll
    for (int j = 0; j < 4; j++) {
        red[wr * 128 + wc * 4 + j]        = s1v[j];
        red[1024 + wr * 128 + wc * 4 + j] = s2v[j];
    }
    __syncthreads();
    if (tid < 128) {
        float s = 0.f;
#pragma unroll
        for (int w = 0; w < 8; w++) s += red[w * 128 + tid];
        atomicAdd(&statp_out[tid], s);
    } else {
        int c = tid - 128;
        float s = 0.f;
#pragma unroll
        for (int w = 0; w < 8; w++) s += red[1024 + w * 128 + c];
        atomicAdd(&statp_out[256 + c], s);
    }
}

// ---------------- final head ----------------
__global__ void k_head_prep(const float* __restrict__ gamma, const float* __restrict__ beta,
                            const float* __restrict__ Wout, const float* __restrict__ bout,
                            const float* __restrict__ statp, float invn) {
    __shared__ float sh[128];
    int c = threadIdx.x;  // 128
    float mean = statp[c] * invn;
    float var  = fmaxf(statp[256 + c] * invn - mean * mean, 0.f);
    float a = gamma[c] * rsqrtf(var + EPSBN);
    g_a[c] = a;
    sh[c] = (beta[c] - mean * a) * Wout[c];
    __syncthreads();
    for (int s = 64; s > 0; s >>= 1) {
        if (c < s) sh[c] += sh[c + s];
        __syncthreads();
    }
    if (c == 0) g_bout[0] = bout[0] + sh[0];
}

__global__ void k_final(const float* __restrict__ Wout, float* __restrict__ out) {
    int warp = (blockIdx.x * blockDim.x + threadIdx.x) >> 5;
    int lane = threadIdx.x & 31;
    if (warp >= NV) return;
    float s = 0.f;
#pragma unroll
    for (int q = 0; q < 4; q++) {
        int c = q * 32 + lane;
        s += g_v[warp * 128 + c] * g_a[c] * Wout[c];
    }
#pragma unroll
    for (int o = 16; o; o >>= 1) s += __shfl_xor_sync(0xffffffffu, s, o);
    if (lane == 0) out[warp] = eluf(s + g_bout[0]);
}

// ---------------- host orchestration ----------------
extern "C" void kernel_launch(void* const* d_in, const int* in_sizes, int n_in,
                              void* d_out, int out_size) {
    const float* inputs   = (const float*)d_in[0];
    // d_in[1] = mask: irrelevant (avg columns fold to beta exactly)
    const int*   Di_rows  = (const int*)d_in[2];
    const int*   Di_cols  = (const int*)d_in[3];
    const float* Di_vals  = (const float*)d_in[4];
    const int*   DiA_rows = (const int*)d_in[5];
    const int*   DiA_cols = (const int*)d_in[6];
    const float* DiA_vals = (const float*)d_in[7];
    const float* W_in  = (const float*)d_in[8];
    const float* b_in  = (const float*)d_in[9];
    const float* g0    = (const float*)d_in[10];
    const float* be0   = (const float*)d_in[11];
    const float* W0    = (const float*)d_in[12];
    const float* b0    = (const float*)d_in[13];
    const float* g1    = (const float*)d_in[14];
    const float* be1   = (const float*)d_in[15];
    const float* Wl1   = (const float*)d_in[16];
    const float* bl1   = (const float*)d_in[17];
    const float* g2    = (const float*)d_in[18];
    const float* be2   = (const float*)d_in[19];
    const float* W_out = (const float*)d_in[20];
    const float* b_out = (const float*)d_in[21];
    float* out = (float*)d_out;
    (void)in_sizes; (void)n_in; (void)out_size;

    float *p_v, *p_ev, *p_ef, *p_ex, *p_Dv, *p_DA, *p_stats;
    cudaGetSymbolAddress((void**)&p_v,     g_v);
    cudaGetSymbolAddress((void**)&p_ev,    g_ev);
    cudaGetSymbolAddress((void**)&p_ef,    g_ef);
    cudaGetSymbolAddress((void**)&p_ex,    g_ex);
    cudaGetSymbolAddress((void**)&p_Dv,    g_Dv);
    cudaGetSymbolAddress((void**)&p_DA,    g_DA);
    cudaGetSymbolAddress((void**)&p_stats, g_stats);
    // one-shot stat buffers, consumer-ordered: layer i -> idx 2i (gemm1), 2i+1 (gemm2);
    // head = 62; indices >= 60 produced-but-unconsumed are harmless dummies.
    auto SB = [&](int i) { return p_stats + (size_t)i * 512; };

    const int GF = (NFC + 63) / 64;
    const int GN = (NV  + 63) / 64;
    const int GS = (NNZT * 8 + 255) / 256;
    const float INV_F = 1.0f / (float)NFC;
    const float INV_N = 1.0f / (float)NV;

    // replay-invariant init
    cudaMemsetAsync(p_stats, 0, (size_t)64 * 512 * sizeof(float));
    cudaMemsetAsync(p_ef, 0, (size_t)NFC * 128 * sizeof(float));   // f(0)=0 -> elu=0
    k_in<<<128, 128>>>(inputs, W_in, b_in, SB(1));                 // ev stats -> L0.gemm2

    for (int i = 0; i < LAYERS; i++) {
        const float* W0i  = W0  + (size_t)i * 256 * 128;
        const float* Wl1i = Wl1 + (size_t)i * 256 * 128;
        int c1 = 2 * i, c2 = 2 * i + 1;
        if ((i & 1) == 0) {
            // ---- DirResNet2 ----
            cudaMemsetAsync(p_Dv, 0, (size_t)NFC * 128 * sizeof(float));
            k_spmm<<<GS, 256>>>(Di_rows, Di_cols, Di_vals, p_ev, p_Dv);
            k_stats128<<<256, 128>>>(p_Dv, NFC, SB(c1), 128);
            // f_out = BNGEMM([ef|Dv]); ef=elu in place; ef stats -> gemm1 two layers on
            k_gemm<16, false><<<GF, 256>>>(p_ef, p_Dv, NFC, W0i, b0 + i * 128,
                                           g0 + i * 256, be0 + i * 256, SB(c1), INV_F,
                                           nullptr, p_ef, SB(c1 + 4));
            cudaMemsetAsync(p_DA, 0, (size_t)NV * 128 * sizeof(float));
            k_spmm<<<GS, 256>>>(DiA_rows, DiA_cols, DiA_vals, p_ef, p_DA);
            k_stats128<<<256, 128>>>(p_DA, NV, SB(c2), 128);
            // v += BNGEMM([ev|DA]); ev=elu(v); ev stats -> next odd gemm1
            k_gemm<16, true><<<GN, 256>>>(p_ev, p_DA, NV, Wl1i, bl1 + i * 128,
                                          g1 + i * 256, be1 + i * 256, SB(c2), INV_N,
                                          p_v, p_ev, SB(c2 + 1));
        } else {
            // ---- AvgResNet2 (avg columns folded; K halved) ----
            k_gemm<8, false><<<GN, 256>>>(p_ev, nullptr, NV, W0i, b0 + i * 128,
                                          g0 + i * 256, be0 + i * 256, SB(c1), INV_N,
                                          nullptr, p_ex, SB(c1 + 1));
            // v += BNGEMM([ex|avg]); ev=elu(v); ev stats -> next even gemm2
            k_gemm<8, true><<<GN, 256>>>(p_ex, nullptr, NV, Wl1i, bl1 + i * 128,
                                         g1 + i * 256, be1 + i * 256, SB(c2), INV_N,
                                         p_v, p_ev, SB(c2 + 2));
        }
    }

    // final head: elu( BN(v) @ W_out + b_out )
    k_stats128<<<256, 128>>>(p_v, NV, SB(62), 0);
    k_head_prep<<<1, 128>>>(g2, be2, W_out, b_out, SB(62), INV_N);
    k_final<<<(NV * 32 + 255) / 256, 256>>>(W_out, out);
}